// round 17
// baseline (speedup 1.0000x reference)
#include <cuda_runtime.h>
#include <cuda_fp16.h>
#include <math.h>

#define NN   50000
#define EE   1600000
#define DIN  128
#define HIDD 128
#define DOUT 64
#define NLL  200000
#define NEG  0.2f

#define SCAN_B 512
#define NBLK   ((NN + SCAN_B - 1) / SCAN_B)   // 98
#define GEMM_BLOCKS ((NN + 127) / 128)        // 391
#define E4_BLOCKS   ((EE / 4 + 255) / 256)    // 1563
#define FIN_BLOCKS  ((NN + 255) / 256)        // 196
#define CVT_BLOCKS  ((NN * 128 / 8 + 255) / 256)  // 3125
#define DEC_BLOCKS  (((NLL + 3) / 4 * 32 + 255) / 256)
#define ZERO_BLOCKS 32

// ---------------- scratch (device globals; no allocation allowed) ----------------
__device__ __half g_a16[NN * HIDD];    // fp16 GEMM input (x16 or agg output)
__device__ __half g_h16[NN * HIDD];    // fp16 GEMM output (gather source)
__device__ __half g_z16[NN * DOUT];    // fp16 final embeddings (decode source)
__device__ float  g_as[NN];
__device__ float  g_ad[NN];
__device__ float  g_dinv[NN];
__device__ int    g_deg[NN];       // zero-initialized at load; re-zeroed by decode
__device__ int    g_cursor[NN];    // same
__device__ int    g_rowloc[NN];
__device__ int    g_rowptr[NN + 1];
__device__ int    g_csrc[EE];
__device__ int    g_bsum[NBLK];

__device__ __forceinline__ float lrelu(float v) { return v > 0.f ? v : NEG * v; }
__device__ __forceinline__ unsigned int smem_u32(const void* p) {
    return (unsigned int)__cvta_generic_to_shared(p);
}

// ---------------- launch 0: degree count + x -> fp16 conversion ----------------
__global__ void prep_kernel(const float* __restrict__ x, const int* __restrict__ edst) {
    int b = blockIdx.x;
    int tid = threadIdx.x;
    if (b < E4_BLOCKS) {
        int i = b * 256 + tid;
        if (i < EE / 4) {
            int4 d = reinterpret_cast<const int4*>(edst)[i];
            atomicAdd(&g_deg[d.x], 1);
            atomicAdd(&g_deg[d.y], 1);
            atomicAdd(&g_deg[d.z], 1);
            atomicAdd(&g_deg[d.w], 1);
        }
        return;
    }
    int i = (b - E4_BLOCKS) * 256 + tid;     // each converts 8 floats
    if (i < NN * 128 / 8) {
        float4 f0 = reinterpret_cast<const float4*>(x)[i * 2];
        float4 f1 = reinterpret_cast<const float4*>(x)[i * 2 + 1];
        __half2 h0 = __floats2half2_rn(f0.x, f0.y);
        __half2 h1 = __floats2half2_rn(f0.z, f0.w);
        __half2 h2 = __floats2half2_rn(f1.x, f1.y);
        __half2 h3 = __floats2half2_rn(f1.z, f1.w);
        uint4 v;
        v.x = *(unsigned int*)&h0; v.y = *(unsigned int*)&h1;
        v.z = *(unsigned int*)&h2; v.w = *(unsigned int*)&h3;
        reinterpret_cast<uint4*>(g_a16)[i] = v;
    }
}

// ---------------- launch 1: per-block local scan (+bsum, +dinv) ----------------
__global__ void scan_partial_kernel() {
    __shared__ int ws[SCAN_B / 32];
    int tid = threadIdx.x;
    int lane = tid & 31, wid = tid >> 5;
    int i = blockIdx.x * SCAN_B + tid;
    int v = (i < NN) ? g_deg[i] : 0;
    if (i < NN) g_dinv[i] = rsqrtf((float)(v + 1));
    int x = v;
    #pragma unroll
    for (int o = 1; o < 32; o <<= 1) {
        int y = __shfl_up_sync(0xffffffffu, x, o);
        if (lane >= o) x += y;
    }
    if (lane == 31) ws[wid] = x;
    __syncthreads();
    if (tid < 32) {
        int w = (tid < SCAN_B / 32) ? ws[tid] : 0;
        #pragma unroll
        for (int o = 1; o < SCAN_B / 32; o <<= 1) {
            int y = __shfl_up_sync(0xffffffffu, w, o);
            if (tid >= o) w += y;
        }
        if (tid < SCAN_B / 32) ws[tid] = w;
    }
    __syncthreads();
    int pref = wid ? ws[wid - 1] : 0;
    int incl = x + pref;
    if (i < NN) g_rowloc[i] = incl - v;
    if (tid == SCAN_B - 1) g_bsum[blockIdx.x] = incl;
}

__device__ __forceinline__ void block_boff(int* s_boff, int* s_ws) {
    int tid = threadIdx.x;
    if (tid < 128) {
        int lane = tid & 31, w4 = tid >> 5;
        int v = (tid < NBLK) ? g_bsum[tid] : 0;
        int x = v;
        #pragma unroll
        for (int o = 1; o < 32; o <<= 1) {
            int y = __shfl_up_sync(0xffffffffu, x, o);
            if (lane >= o) x += y;
        }
        if (lane == 31) s_ws[w4] = x;
    }
    __syncthreads();
    if (tid < 32) {
        int w = (tid < 4) ? s_ws[tid] : 0;
        #pragma unroll
        for (int o = 1; o < 4; o <<= 1) {
            int y = __shfl_up_sync(0xffffffffu, w, o);
            if (tid >= o) w += y;
        }
        if (tid < 4) s_ws[tid] = w;
    }
    __syncthreads();
    if (tid < 128) {
        int lane = tid & 31, w4 = tid >> 5;
        int v = (tid < NBLK) ? g_bsum[tid] : 0;
        int x = v;
        #pragma unroll
        for (int o = 1; o < 32; o <<= 1) {
            int y = __shfl_up_sync(0xffffffffu, x, o);
            if (lane >= o) x += y;
        }
        int pref = w4 ? s_ws[w4 - 1] : 0;
        if (tid < NBLK) s_boff[tid] = x + pref - v;
    }
    __syncthreads();
}

// ---------------- HGEMM (+fused scores epilogue, +optional fused CSR fill blocks) ----------------
// g_h16[M,BN] = g_a16[M,128] * W[128,BN] via mma.sync fp16->fp32.
// Tile 128xBN, 8 warps (warp tile 32 x BN/2), K in 2 chunks of 64.
template<int BN, bool FUSE, bool FILL>
__global__ __launch_bounds__(256, 2)
void hgemm_kernel(const float* __restrict__ W,
                  const float* __restrict__ avs, const float* __restrict__ avd,
                  const int* __restrict__ esrc, const int* __restrict__ edst) {
    if (FILL && blockIdx.x >= GEMM_BLOCKS) {
        // overlapped CSR fill + rowptr finalize (atomic/L2-bound; hides under tensor blocks)
        __shared__ int s_boff[NBLK];
        __shared__ int s_ws4[4];
        block_boff(s_boff, s_ws4);
        int tid = threadIdx.x;
        int b = blockIdx.x - GEMM_BLOCKS;
        if (b < E4_BLOCKS) {
            int i = b * 256 + tid;
            if (i < EE / 4) {
                int4 s = reinterpret_cast<const int4*>(esrc)[i];
                int4 d = reinterpret_cast<const int4*>(edst)[i];
                int p;
                p = atomicAdd(&g_cursor[d.x], 1); g_csrc[g_rowloc[d.x] + s_boff[d.x >> 9] + p] = s.x;
                p = atomicAdd(&g_cursor[d.y], 1); g_csrc[g_rowloc[d.y] + s_boff[d.y >> 9] + p] = s.y;
                p = atomicAdd(&g_cursor[d.z], 1); g_csrc[g_rowloc[d.z] + s_boff[d.z >> 9] + p] = s.z;
                p = atomicAdd(&g_cursor[d.w], 1); g_csrc[g_rowloc[d.w] + s_boff[d.w >> 9] + p] = s.w;
            }
        } else {
            int i = (b - E4_BLOCKS) * 256 + tid;
            if (i < NN) g_rowptr[i] = g_rowloc[i] + s_boff[i >> 9];
            if (b == E4_BLOCKS && tid == 0) g_rowptr[NN] = EE;
        }
        return;
    }
    constexpr int KC = 64;
    constexpr int WN = BN / 2;
    constexpr int NT = WN / 8;
    __shared__ __align__(16) __half sA[128][KC];
    __shared__ __align__(16) __half sB[KC][BN];
    __shared__ float s_as[128], s_ad[128];
    int tid = threadIdx.x;
    int wid = tid >> 5, lane = tid & 31;
    int warp_m = wid & 3, warp_n = wid >> 2;
    int block_row = blockIdx.x * 128;

    if (FUSE && tid < 128) { s_as[tid] = 0.f; s_ad[tid] = 0.f; }

    float c[2][NT][4];
    #pragma unroll
    for (int mt = 0; mt < 2; mt++)
        #pragma unroll
        for (int nt = 0; nt < NT; nt++)
            #pragma unroll
            for (int q = 0; q < 4; q++) c[mt][nt][q] = 0.f;

    #pragma unroll
    for (int kc = 0; kc < 128; kc += KC) {
        #pragma unroll
        for (int i = 0; i < 4; i++) {
            int idx = tid + i * 256;
            int row = idx >> 3;
            int ck = idx & 7;
            uint4 v = make_uint4(0u, 0u, 0u, 0u);
            if (block_row + row < NN)
                v = *reinterpret_cast<const uint4*>(
                    &g_a16[(size_t)(block_row + row) * 128 + kc + ck * 8]);
            *reinterpret_cast<uint4*>(&sA[row][(ck ^ (row & 7)) * 8]) = v;
        }
        #pragma unroll
        for (int i = 0; i < (KC * BN / 8) / 256; i++) {
            int idx = tid + i * 256;
            int k = idx / (BN / 8);
            int ck = idx % (BN / 8);
            float4 f0 = *reinterpret_cast<const float4*>(&W[(size_t)(kc + k) * BN + ck * 8]);
            float4 f1 = *reinterpret_cast<const float4*>(&W[(size_t)(kc + k) * BN + ck * 8 + 4]);
            __half2 h0 = __floats2half2_rn(f0.x, f0.y);
            __half2 h1 = __floats2half2_rn(f0.z, f0.w);
            __half2 h2 = __floats2half2_rn(f1.x, f1.y);
            __half2 h3 = __floats2half2_rn(f1.z, f1.w);
            uint4 v;
            v.x = *(unsigned int*)&h0; v.y = *(unsigned int*)&h1;
            v.z = *(unsigned int*)&h2; v.w = *(unsigned int*)&h3;
            *reinterpret_cast<uint4*>(&sB[k][(ck ^ (k & 7)) * 8]) = v;
        }
        __syncthreads();
        #pragma unroll
        for (int k16 = 0; k16 < KC / 16; k16++) {
            unsigned int af[2][4];
            #pragma unroll
            for (int mt = 0; mt < 2; mt++) {
                int row = warp_m * 32 + mt * 16 + (lane & 15);
                int ck = k16 * 2 + (lane >> 4);
                unsigned int addr = smem_u32(&sA[row][(ck ^ (row & 7)) * 8]);
                asm volatile("ldmatrix.sync.aligned.m8n8.x4.shared.b16 {%0,%1,%2,%3}, [%4];"
                    : "=r"(af[mt][0]), "=r"(af[mt][1]), "=r"(af[mt][2]), "=r"(af[mt][3])
                    : "r"(addr));
            }
            unsigned int bf[NT][2];
            #pragma unroll
            for (int nt2 = 0; nt2 < NT / 2; nt2++) {
                int k = k16 * 16 + (lane & 15);
                int ncol = warp_n * WN + nt2 * 16 + (lane >> 4) * 8;
                int ck = ncol >> 3;
                unsigned int addr = smem_u32(&sB[k][(ck ^ (k & 7)) * 8]);
                unsigned int r0, r1, r2, r3;
                asm volatile("ldmatrix.sync.aligned.m8n8.x4.trans.shared.b16 {%0,%1,%2,%3}, [%4];"
                    : "=r"(r0), "=r"(r1), "=r"(r2), "=r"(r3) : "r"(addr));
                bf[nt2 * 2][0] = r0;     bf[nt2 * 2][1] = r1;
                bf[nt2 * 2 + 1][0] = r2; bf[nt2 * 2 + 1][1] = r3;
            }
            #pragma unroll
            for (int mt = 0; mt < 2; mt++)
                #pragma unroll
                for (int nt = 0; nt < NT; nt++)
                    asm volatile(
                        "mma.sync.aligned.m16n8k16.row.col.f32.f16.f16.f32 "
                        "{%0,%1,%2,%3}, {%4,%5,%6,%7}, {%8,%9}, {%0,%1,%2,%3};"
                        : "+f"(c[mt][nt][0]), "+f"(c[mt][nt][1]),
                          "+f"(c[mt][nt][2]), "+f"(c[mt][nt][3])
                        : "r"(af[mt][0]), "r"(af[mt][1]), "r"(af[mt][2]), "r"(af[mt][3]),
                          "r"(bf[nt][0]), "r"(bf[nt][1]));
        }
        __syncthreads();
    }

    int qr = lane >> 2;
    int qc = lane & 3;
    #pragma unroll
    for (int mt = 0; mt < 2; mt++) {
        int r0 = block_row + warp_m * 32 + mt * 16 + qr;
        int r1 = r0 + 8;
        #pragma unroll
        for (int nt = 0; nt < NT; nt++) {
            int col = warp_n * WN + nt * 8 + qc * 2;
            if (r0 < NN) {
                __half2 h = __floats2half2_rn(c[mt][nt][0], c[mt][nt][1]);
                *reinterpret_cast<unsigned int*>(&g_h16[(size_t)r0 * BN + col]) =
                    *(unsigned int*)&h;
            }
            if (r1 < NN) {
                __half2 h = __floats2half2_rn(c[mt][nt][2], c[mt][nt][3]);
                *reinterpret_cast<unsigned int*>(&g_h16[(size_t)r1 * BN + col]) =
                    *(unsigned int*)&h;
            }
        }
    }

    if (FUSE) {
        // scores from fp32 fragments: partial dots -> smem atomics (8 threads/row)
        #pragma unroll
        for (int mt = 0; mt < 2; mt++) {
            float s0 = 0.f, d0 = 0.f, s1 = 0.f, d1 = 0.f;
            #pragma unroll
            for (int nt = 0; nt < NT; nt++) {
                int col = warp_n * WN + nt * 8 + qc * 2;
                float a0 = avs[col], a1 = avs[col + 1];
                float e0 = avd[col], e1 = avd[col + 1];
                s0 = fmaf(c[mt][nt][0], a0, fmaf(c[mt][nt][1], a1, s0));
                d0 = fmaf(c[mt][nt][0], e0, fmaf(c[mt][nt][1], e1, d0));
                s1 = fmaf(c[mt][nt][2], a0, fmaf(c[mt][nt][3], a1, s1));
                d1 = fmaf(c[mt][nt][2], e0, fmaf(c[mt][nt][3], e1, d1));
            }
            int lr0 = warp_m * 32 + mt * 16 + qr;
            atomicAdd(&s_as[lr0], s0);     atomicAdd(&s_ad[lr0], d0);
            atomicAdd(&s_as[lr0 + 8], s1); atomicAdd(&s_ad[lr0 + 8], d1);
        }
        __syncthreads();
        if (tid < 128 && block_row + tid < NN) {
            g_as[block_row + tid] = s_as[tid];
            g_ad[block_row + tid] = s_ad[tid];
        }
    }
}

// ---------------- GAT aggregate: fused softmax, fp16 gather, smem-staged (s,p); fp16 output ----------------
__global__ __launch_bounds__(256)
void gat_agg_kernel(const float* __restrict__ bias) {
    __shared__ float2 s_sp[8][32];
    int warp = (blockIdx.x * blockDim.x + threadIdx.x) >> 5;
    int w = (threadIdx.x >> 5);
    int lane = threadIdx.x & 31;
    if (warp >= NN) return;
    int node = warp;
    int rs = g_rowptr[node], re = g_rowptr[node + 1];
    float adi = g_ad[node];
    float pself = __expf(lrelu(g_as[node] + adi));

    const uint2* h2 = reinterpret_cast<const uint2*>(g_h16);
    uint2 selfraw = h2[(size_t)node * 32 + lane];
    float2 sf01 = __half22float2(*reinterpret_cast<__half2*>(&selfraw.x));
    float2 sf23 = __half22float2(*reinterpret_cast<__half2*>(&selfraw.y));
    float4 acc = make_float4(pself * sf01.x, pself * sf01.y, pself * sf23.x, pself * sf23.y);
    float ssum_l = (lane == 0) ? pself : 0.f;

    for (int base = rs; base < re; base += 32) {
        int j = base + lane;
        int srcv = 0; float pv = 0.f;
        if (j < re) {
            srcv = g_csrc[j];
            pv = __expf(lrelu(g_as[srcv] + adi));
        }
        ssum_l += pv;
        __syncwarp();
        s_sp[w][lane] = make_float2(__int_as_float(srcv), pv);
        __syncwarp();
        int cnt = re - base;
        if (cnt >= 32) {
            #pragma unroll
            for (int t = 0; t < 32; t++) {
                float2 sp = s_sp[w][t];
                int s = __float_as_int(sp.x);
                float p = sp.y;
                uint2 raw = h2[(size_t)s * 32 + lane];
                float2 f01 = __half22float2(*reinterpret_cast<__half2*>(&raw.x));
                float2 f23 = __half22float2(*reinterpret_cast<__half2*>(&raw.y));
                acc.x = fmaf(p, f01.x, acc.x);
                acc.y = fmaf(p, f01.y, acc.y);
                acc.z = fmaf(p, f23.x, acc.z);
                acc.w = fmaf(p, f23.y, acc.w);
            }
        } else {
            for (int t = 0; t < cnt; t++) {
                float2 sp = s_sp[w][t];
                int s = __float_as_int(sp.x);
                float p = sp.y;
                uint2 raw = h2[(size_t)s * 32 + lane];
                float2 f01 = __half22float2(*reinterpret_cast<__half2*>(&raw.x));
                float2 f23 = __half22float2(*reinterpret_cast<__half2*>(&raw.y));
                acc.x = fmaf(p, f01.x, acc.x);
                acc.y = fmaf(p, f01.y, acc.y);
                acc.z = fmaf(p, f23.x, acc.z);
                acc.w = fmaf(p, f23.y, acc.w);
            }
        }
    }
    float ssum = ssum_l;
    #pragma unroll
    for (int o = 16; o; o >>= 1) ssum += __shfl_xor_sync(0xffffffffu, ssum, o);

    float inv = 1.f / ssum;
    float4 bv = reinterpret_cast<const float4*>(bias)[lane];
    float ox = fmaxf(fmaf(acc.x, inv, bv.x), 0.f);
    float oy = fmaxf(fmaf(acc.y, inv, bv.y), 0.f);
    float oz = fmaxf(fmaf(acc.z, inv, bv.z), 0.f);
    float ow = fmaxf(fmaf(acc.w, inv, bv.w), 0.f);
    __half2 ho0 = __floats2half2_rn(ox, oy);
    __half2 ho1 = __floats2half2_rn(oz, ow);
    uint2 st;
    st.x = *(unsigned int*)&ho0;
    st.y = *(unsigned int*)&ho1;
    reinterpret_cast<uint2*>(g_a16)[(size_t)node * 32 + lane] = st;   // next GEMM input
}

// ---------------- GCN aggregate: fp16 gather, fp16 z output (decode source) ----------------
__global__ __launch_bounds__(256)
void gcn_agg_kernel(const float* __restrict__ bias) {
    __shared__ float2 s_sp[8][32];
    int warp = (blockIdx.x * blockDim.x + threadIdx.x) >> 5;
    int w = (threadIdx.x >> 5);
    int lane = threadIdx.x & 31;
    if (warp >= NN) return;
    int node = warp;
    int rs = g_rowptr[node], re = g_rowptr[node + 1];
    float di = g_dinv[node];
    const unsigned int* h1 = reinterpret_cast<const unsigned int*>(g_h16);
    unsigned int selfraw = h1[(size_t)node * 32 + lane];
    float2 gv = __half22float2(*reinterpret_cast<__half2*>(&selfraw));
    float nself = di * di;
    float2 acc = make_float2(nself * gv.x, nself * gv.y);
    for (int base = rs; base < re; base += 32) {
        int j = base + lane;
        int srcv = 0; float nrm = 0.f;
        if (j < re) { srcv = g_csrc[j]; nrm = di * g_dinv[srcv]; }
        __syncwarp();
        s_sp[w][lane] = make_float2(__int_as_float(srcv), nrm);
        __syncwarp();
        int cnt = re - base;
        if (cnt >= 32) {
            #pragma unroll
            for (int t = 0; t < 32; t++) {
                float2 sp = s_sp[w][t];
                int s = __float_as_int(sp.x);
                float p = sp.y;
                unsigned int raw = h1[(size_t)s * 32 + lane];
                float2 v = __half22float2(*reinterpret_cast<__half2*>(&raw));
                acc.x = fmaf(p, v.x, acc.x);
                acc.y = fmaf(p, v.y, acc.y);
            }
        } else {
            for (int t = 0; t < cnt; t++) {
                float2 sp = s_sp[w][t];
                int s = __float_as_int(sp.x);
                float p = sp.y;
                unsigned int raw = h1[(size_t)s * 32 + lane];
                float2 v = __half22float2(*reinterpret_cast<__half2*>(&raw));
                acc.x = fmaf(p, v.x, acc.x);
                acc.y = fmaf(p, v.y, acc.y);
            }
        }
    }
    float2 bv = reinterpret_cast<const float2*>(bias)[lane];
    __half2 hz = __floats2half2_rn(acc.x + bv.x, acc.y + bv.y);
    reinterpret_cast<unsigned int*>(g_z16)[(size_t)node * 32 + lane] =
        *(unsigned int*)&hz;
}

// ---------------- decode (fp16 z): out[e] = dot(z[a], z[b]), 8 lanes/edge ----------------
__global__ void decode_kernel(const int* __restrict__ eli, float* __restrict__ out) {
    if (blockIdx.x >= DEC_BLOCKS) {
        int i = (blockIdx.x - DEC_BLOCKS) * 256 + threadIdx.x;
        for (int k = i; k < NN; k += ZERO_BLOCKS * 256) { g_deg[k] = 0; g_cursor[k] = 0; }
        return;
    }
    int gtid = blockIdx.x * blockDim.x + threadIdx.x;
    int warp = gtid >> 5;
    int lane = threadIdx.x & 31;
    int sub = lane >> 3, l8 = lane & 7;
    int e = warp * 4 + sub;
    if (e >= NLL) return;
    int a = eli[e];
    int b = eli[NLL + e];
    const uint4* z8 = reinterpret_cast<const uint4*>(g_z16);   // 8 halves per uint4
    uint4 va = z8[(size_t)a * 8 + l8];
    uint4 vb = z8[(size_t)b * 8 + l8];
    float2 a0 = __half22float2(*reinterpret_cast<__half2*>(&va.x));
    float2 a1 = __half22float2(*reinterpret_cast<__half2*>(&va.y));
    float2 a2 = __half22float2(*reinterpret_cast<__half2*>(&va.z));
    float2 a3 = __half22float2(*reinterpret_cast<__half2*>(&va.w));
    float2 b0 = __half22float2(*reinterpret_cast<__half2*>(&vb.x));
    float2 b1 = __half22float2(*reinterpret_cast<__half2*>(&vb.y));
    float2 b2 = __half22float2(*reinterpret_cast<__half2*>(&vb.z));
    float2 b3 = __half22float2(*reinterpret_cast<__half2*>(&vb.w));
    float dot = a0.x * b0.x + a0.y * b0.y + a1.x * b1.x + a1.y * b1.y
              + a2.x * b2.x + a2.y * b2.y + a3.x * b3.x + a3.y * b3.y;
    dot += __shfl_xor_sync(0xffffffffu, dot, 4);
    dot += __shfl_xor_sync(0xffffffffu, dot, 2);
    dot += __shfl_xor_sync(0xffffffffu, dot, 1);
    if (l8 == 0) out[e] = dot;
}

// ---------------- launch ----------------
extern "C" void kernel_launch(void* const* d_in, const int* in_sizes, int n_in,
                              void* d_out, int out_size) {
    const float* x   = (const float*)d_in[0];
    const int*   ei  = (const int*)d_in[1];          // [2,E]
    const int*   eli = (const int*)d_in[2];          // [2,NL]
    const float* W1  = (const float*)d_in[3];
    const float* a1s = (const float*)d_in[4];
    const float* a1d = (const float*)d_in[5];
    const float* b1  = (const float*)d_in[6];
    const float* W2  = (const float*)d_in[7];
    const float* a2s = (const float*)d_in[8];
    const float* a2d = (const float*)d_in[9];
    const float* b2  = (const float*)d_in[10];
    const float* W3  = (const float*)d_in[11];
    const float* a3s = (const float*)d_in[12];
    const float* a3d = (const float*)d_in[13];
    const float* b3  = (const float*)d_in[14];
    const float* W4  = (const float*)d_in[15];
    const float* b4  = (const float*)d_in[16];
    float* out = (float*)d_out;

    const int* e_src = ei;
    const int* e_dst = ei + EE;

    const int TB = 256;
    int node_warp_blocks = (NN * 32 + TB - 1) / TB;

    // 0: degree count + x->fp16
    prep_kernel<<<E4_BLOCKS + CVT_BLOCKS, TB>>>(x, e_dst);
    // 1: per-block local scan (+dinv, +bsum)
    scan_partial_kernel<<<NBLK, SCAN_B>>>();
    // 2: hgemm1 + fused scores + fused CSR fill/finalize
    hgemm_kernel<HIDD, true, true><<<GEMM_BLOCKS + E4_BLOCKS + FIN_BLOCKS, 256>>>(
        W1, a1s, a1d, e_src, e_dst);
    // 3: gat layer 1  <- profiled launch index (control ~44us)
    gat_agg_kernel<<<node_warp_blocks, TB>>>(b1);

    // layer 2
    hgemm_kernel<HIDD, true, false><<<GEMM_BLOCKS, 256>>>(W2, a2s, a2d, nullptr, nullptr);
    gat_agg_kernel<<<node_warp_blocks, TB>>>(b2);

    // layer 3
    hgemm_kernel<HIDD, true, false><<<GEMM_BLOCKS, 256>>>(W3, a3s, a3d, nullptr, nullptr);
    gat_agg_kernel<<<node_warp_blocks, TB>>>(b3);

    // GCN
    hgemm_kernel<DOUT, false, false><<<GEMM_BLOCKS, 256>>>(W4, nullptr, nullptr, nullptr, nullptr);
    gcn_agg_kernel<<<node_warp_blocks, TB>>>(b4);

    // decode + re-zero deg/cursor
    decode_kernel<<<DEC_BLOCKS + ZERO_BLOCKS, TB>>>(eli, out);
}